// round 11
// baseline (speedup 1.0000x reference)
#include <cuda_runtime.h>
#include <cuda_fp16.h>
#include <cstdint>

// ---------------- Problem constants ----------------
#define D_MODEL 1024
#define NHEAD   16
#define DHEAD   64
#define DFF     4096
#define BB      2
#define SS      2048
#define RR      25
#define WW      51
#define KCLIP   5
#define NTOK    (BB * SS)

// ---------------- Scratch ----------------
__device__ float  g_qkv[(size_t)NTOK * 3 * D_MODEL];   // fp32 Q|K|V (ldc=3072)
__device__ float  g_c1 [(size_t)NTOK * D_MODEL];
__device__ float  g_x1 [(size_t)NTOK * D_MODEL];
__device__ __half g_srch[(size_t)NTOK * D_MODEL];
__device__ __half g_zh  [(size_t)NTOK * D_MODEL];
__device__ __half g_x1h [(size_t)NTOK * D_MODEL];
__device__ __half g_c2h [(size_t)NTOK * DFF];
__device__ __half g_wqkvh[(size_t)3 * D_MODEL * D_MODEL]; // wq|wk|wv rows
__device__ __half g_woh[(size_t)D_MODEL * D_MODEL];
__device__ __half g_w1h[(size_t)DFF * D_MODEL];
__device__ __half g_w2h[(size_t)D_MODEL * DFF];

// ---------------- helpers ----------------
__device__ __forceinline__ uint32_t smem_u32(const void* p) {
    uint32_t a;
    asm("{ .reg .u64 t; cvta.to.shared.u64 t, %1; cvt.u32.u64 %0, t; }" : "=r"(a) : "l"(p));
    return a;
}
__device__ __forceinline__ void cpasync16(uint32_t s, const void* g) {
    asm volatile("cp.async.cg.shared.global [%0], [%1], 16;\n" :: "r"(s), "l"(g));
}
__device__ __forceinline__ void ldm_x4(uint32_t& r0, uint32_t& r1, uint32_t& r2, uint32_t& r3,
                                       uint32_t addr) {
    asm volatile("ldmatrix.sync.aligned.m8n8.x4.shared.b16 {%0,%1,%2,%3}, [%4];"
                 : "=r"(r0), "=r"(r1), "=r"(r2), "=r"(r3) : "r"(addr));
}
__device__ __forceinline__ void mma16816(float* d, const uint32_t* a, uint32_t b0, uint32_t b1) {
    asm volatile("mma.sync.aligned.m16n8k16.row.col.f32.f16.f16.f32 "
                 "{%0,%1,%2,%3}, {%4,%5,%6,%7}, {%8,%9}, {%0,%1,%2,%3};"
                 : "+f"(d[0]), "+f"(d[1]), "+f"(d[2]), "+f"(d[3])
                 : "r"(a[0]), "r"(a[1]), "r"(a[2]), "r"(a[3]), "r"(b0), "r"(b1));
}

// ---------------- fp16 GEMM: 4-stage, single-sync pipeline ----------------
// C[M,N] = A[M,K] @ B[N,K]^T ; mode 0: fp32 out; 1: half bias+relu; 2: half bias
#define ST_A 10240              // 128 rows * 80B
#define ST_STAGE 20480          // A + B
#define NST 4
#define HGEMM_SMEM (NST * ST_STAGE)   // 81920

__global__ __launch_bounds__(256, 2) void hgemm(
    const __half* __restrict__ A, const __half* __restrict__ B,
    float* __restrict__ Cf, __half* __restrict__ Ch,
    int M, int N, int K, int ldc, int mode, const float* __restrict__ bias)
{
    extern __shared__ char smem[];
    const uint32_t sb = smem_u32(smem);
    const int tid = threadIdx.x;
    const int bm = blockIdx.y * 128;
    const int bn = blockIdx.x * 128;
    const int niter = K >> 5;

    const int pr = tid >> 1;            // row 0..127
    const int pc = (tid & 1) * 2;       // chunk base 0 or 2
    const __half* Agp = A + (size_t)(bm + pr) * K + pc * 8;
    const __half* Bgp = B + (size_t)(bn + pr) * K + pc * 8;
    const uint32_t sOff = (uint32_t)(pr * 5 + pc) * 16;

#define LOADSTAGE(s, it) do {                                     \
        uint32_t as_ = sb + (s) * ST_STAGE + sOff;                \
        const __half* ag_ = Agp + (size_t)(it) * 32;              \
        const __half* bg_ = Bgp + (size_t)(it) * 32;              \
        cpasync16(as_,            ag_);                           \
        cpasync16(as_ + 16,       ag_ + 8);                       \
        cpasync16(as_ + ST_A,     bg_);                           \
        cpasync16(as_ + ST_A + 16, bg_ + 8);                      \
    } while (0)
#define COMMIT() asm volatile("cp.async.commit_group;\n")

    const int warp = tid >> 5;
    const int lane = tid & 31;
    const int wm = (warp & 1) * 64;
    const int wn = (warp >> 1) * 32;
    const int grp = lane >> 3;
    const int lr  = lane & 7;
    const int lrow = (grp & 1) * 8 + lr;
    const int lchk = grp >> 1;

    float acc[4][4][4];
#pragma unroll
    for (int i = 0; i < 4; i++)
#pragma unroll
        for (int j = 0; j < 4; j++)
#pragma unroll
            for (int t = 0; t < 4; t++) acc[i][j][t] = 0.f;

    LOADSTAGE(0, 0); COMMIT();
    LOADSTAGE(1, 1); COMMIT();

    for (int it = 0; it < niter; it++) {
        if (it + 2 < niter) LOADSTAGE((it + 2) & 3, it + 2);
        COMMIT();
        asm volatile("cp.async.wait_group 2;\n");
        __syncthreads();

        const uint32_t aS = sb + (it & 3) * ST_STAGE;
        const uint32_t bS = aS + ST_A;
#pragma unroll
        for (int ks = 0; ks < 2; ks++) {
            uint32_t af[4][4], bf[2][4];
#pragma unroll
            for (int mt = 0; mt < 4; mt++) {
                uint32_t addr = aS + (uint32_t)(((wm + mt * 16 + lrow) * 5 + ks * 2 + lchk) * 16);
                ldm_x4(af[mt][0], af[mt][1], af[mt][2], af[mt][3], addr);
            }
#pragma unroll
            for (int nc = 0; nc < 2; nc++) {
                uint32_t addr = bS + (uint32_t)(((wn + nc * 16 + lrow) * 5 + ks * 2 + lchk) * 16);
                ldm_x4(bf[nc][0], bf[nc][1], bf[nc][2], bf[nc][3], addr);
            }
#pragma unroll
            for (int mt = 0; mt < 4; mt++)
#pragma unroll
                for (int nj = 0; nj < 4; nj++) {
                    int nc = nj >> 1, sub = nj & 1;
                    mma16816(acc[mt][nj], af[mt], bf[nc][sub], bf[nc][sub + 2]);
                }
        }
    }
#undef LOADSTAGE
#undef COMMIT

    const int qrow = lane >> 2;
    const int qcol = (lane & 3) * 2;
#pragma unroll
    for (int mt = 0; mt < 4; mt++) {
        const int row0 = bm + wm + mt * 16 + qrow;
#pragma unroll
        for (int nj = 0; nj < 4; nj++) {
            const int col = bn + wn + nj * 8 + qcol;
            if (mode == 0) {
                *(float2*)(Cf + (size_t)row0 * ldc + col) =
                    make_float2(acc[mt][nj][0], acc[mt][nj][1]);
                *(float2*)(Cf + (size_t)(row0 + 8) * ldc + col) =
                    make_float2(acc[mt][nj][2], acc[mt][nj][3]);
            } else {
                float b0 = bias[col], b1 = bias[col + 1];
                float v0 = acc[mt][nj][0] + b0, v1 = acc[mt][nj][1] + b1;
                float v2 = acc[mt][nj][2] + b0, v3 = acc[mt][nj][3] + b1;
                if (mode == 1) {
                    v0 = fmaxf(v0, 0.f); v1 = fmaxf(v1, 0.f);
                    v2 = fmaxf(v2, 0.f); v3 = fmaxf(v3, 0.f);
                }
                *(__half2*)(Ch + (size_t)row0 * ldc + col) = __floats2half2_rn(v0, v1);
                *(__half2*)(Ch + (size_t)(row0 + 8) * ldc + col) = __floats2half2_rn(v2, v3);
            }
        }
    }
}

// ---------------- merged fp32 -> fp16 convert (all operands, one launch) ----------------
#define SEG0 1048576   // src end (float4 units)
#define SEG1 1310720   // wq end
#define SEG2 1572864   // wk end
#define SEG3 1835008   // wv end
#define SEG4 2097152   // wo end
#define SEG5 3145728   // w1 end
#define SEG6 4194304   // w2 end
__global__ void convert_all_kernel(
    const float* __restrict__ src, const float* __restrict__ wq,
    const float* __restrict__ wk, const float* __restrict__ wv,
    const float* __restrict__ wo, const float* __restrict__ w1,
    const float* __restrict__ w2,
    __half* __restrict__ srch, __half* __restrict__ wqkvh,
    __half* __restrict__ woh, __half* __restrict__ w1h, __half* __restrict__ w2h)
{
    int i = blockIdx.x * blockDim.x + threadIdx.x;
    const float* s; __half* d; int off;
    if      (i < SEG0) { s = src; d = srch;  off = i; }
    else if (i < SEG1) { s = wq;  d = wqkvh; off = i - SEG0; }
    else if (i < SEG2) { s = wk;  d = wqkvh + (size_t)D_MODEL * D_MODEL; off = i - SEG1; }
    else if (i < SEG3) { s = wv;  d = wqkvh + 2 * (size_t)D_MODEL * D_MODEL; off = i - SEG2; }
    else if (i < SEG4) { s = wo;  d = woh;  off = i - SEG3; }
    else if (i < SEG5) { s = w1;  d = w1h;  off = i - SEG4; }
    else if (i < SEG6) { s = w2;  d = w2h;  off = i - SEG5; }
    else return;
    float4 v = ((const float4*)s)[off];
    ((__half2*)d)[off * 2 + 0] = __floats2half2_rn(v.x, v.y);
    ((__half2*)d)[off * 2 + 1] = __floats2half2_rn(v.z, v.w);
}

// ---------------- Windowed relative attention (fp32, vectorized smem) ----------------
#define TS 64
#define KROWS (TS + 2 * RR)   // 114
#define STR 68                // floats per row: 272B, 16B-aligned, conflict-free LDS.128
#define ATTN_SMEM ((KROWS * 2 + TS + 11) * STR * 4)

__global__ __launch_bounds__(256) void attn_kernel(
    const float* __restrict__ qkv,
    const float* __restrict__ bq, const float* __restrict__ bk,
    const float* __restrict__ bv, const float* __restrict__ rel,
    __half* __restrict__ zh)
{
    extern __shared__ float sm[];
    float* ks = sm;                   // KROWS x STR
    float* vs = ks + KROWS * STR;     // KROWS x STR
    float* qs = vs + KROWS * STR;     // TS x STR
    float* rs = qs + TS * STR;        // 11 x STR

    const int h  = blockIdx.y;
    const int b  = blockIdx.z;
    const int s0 = blockIdx.x * TS;
    const int tid = threadIdx.x;
    const size_t baseTok = (size_t)b * SS;
    const int hoff = h * DHEAD;

    // K, V window rows (16 float4 chunks per row)
    for (int idx = tid; idx < KROWS * 16; idx += 256) {
        int i = idx >> 4;
        int d = (idx & 15);
        int t = min(max(s0 - RR + i, 0), SS - 1);
        const float* row = qkv + (baseTok + t) * (3 * D_MODEL);
        float4 k4 = *(const float4*)(row + D_MODEL + hoff + d * 4);
        float4 b4 = *(const float4*)(bk + hoff + d * 4);
        *(float4*)(ks + i * STR + d * 4) =
            make_float4(k4.x + b4.x, k4.y + b4.y, k4.z + b4.z, k4.w + b4.w);
        float4 v4 = *(const float4*)(row + 2 * D_MODEL + hoff + d * 4);
        float4 c4 = *(const float4*)(bv + hoff + d * 4);
        *(float4*)(vs + i * STR + d * 4) =
            make_float4(v4.x + c4.x, v4.y + c4.y, v4.z + c4.z, v4.w + c4.w);
    }
    // Q rows
    for (int idx = tid; idx < TS * 16; idx += 256) {
        int i = idx >> 4;
        int d = (idx & 15);
        float4 q4 = *(const float4*)(qkv + (baseTok + s0 + i) * (3 * D_MODEL) + hoff + d * 4);
        float4 b4 = *(const float4*)(bq + hoff + d * 4);
        *(float4*)(qs + i * STR + d * 4) =
            make_float4(q4.x + b4.x, q4.y + b4.y, q4.z + b4.z, q4.w + b4.w);
    }
    // rel rows
    for (int idx = tid; idx < 11 * 16; idx += 256) {
        int r = idx >> 4;
        int d = (idx & 15);
        *(float4*)(rs + r * STR + d * 4) = *(const float4*)(rel + r * DHEAD + d * 4);
    }
    __syncthreads();

    const int warp = tid >> 5;
    const int lane = tid & 31;
    const float scale = 0.125f;

    for (int qi = warp; qi < TS; qi += 8) {
        const int sq = s0 + qi;
        const float4* q4 = (const float4*)(qs + qi * STR);

        // hoisted q . rel[rid] (lanes 0..10)
        float qr = 0.f;
        if (lane < 11) {
            const float4* rp = (const float4*)(rs + lane * STR);
#pragma unroll
            for (int i = 0; i < 16; i++) {
                float4 qv = q4[i], rv = rp[i];
                qr = fmaf(qv.x, rv.x, qr); qr = fmaf(qv.y, rv.y, qr);
                qr = fmaf(qv.z, rv.z, qr); qr = fmaf(qv.w, rv.w, qr);
            }
        }

        const int w0 = lane;
        const int w1 = lane + 32;
        const bool has1 = (w1 < WW);
        int rid0 = min(max(w0 - RR, -KCLIP), KCLIP) + KCLIP;
        int rid1 = min(max(w1 - RR, -KCLIP), KCLIP) + KCLIP;
        float qr0 = __shfl_sync(0xffffffffu, qr, rid0);
        float qr1 = __shfl_sync(0xffffffffu, qr, rid1);
        const float4* k0p = (const float4*)(ks + (qi + w0) * STR);
        const float4* k1p = (const float4*)(ks + (qi + (has1 ? w1 : 0)) * STR);

        float a0 = 0.f, a1 = 0.f;
#pragma unroll
        for (int i = 0; i < 16; i++) {
            float4 qv = q4[i], f0 = k0p[i], f1 = k1p[i];
            a0 = fmaf(qv.x, f0.x, a0); a0 = fmaf(qv.y, f0.y, a0);
            a0 = fmaf(qv.z, f0.z, a0); a0 = fmaf(qv.w, f0.w, a0);
            a1 = fmaf(qv.x, f1.x, a1); a1 = fmaf(qv.y, f1.y, a1);
            a1 = fmaf(qv.z, f1.z, a1); a1 = fmaf(qv.w, f1.w, a1);
        }
        a0 += qr0;
        a1 += qr1;
        int j0 = sq + w0 - RR;
        int j1 = sq + w1 - RR;
        float sc0 = (j0 >= 0 && j0 < SS) ? a0 * scale : -1e30f;
        float sc1 = (has1 && j1 >= 0 && j1 < SS) ? a1 * scale : -1e30f;

        float m = fmaxf(sc0, sc1);
#pragma unroll
        for (int o = 16; o; o >>= 1) m = fmaxf(m, __shfl_xor_sync(0xffffffffu, m, o));
        float p0 = __expf(sc0 - m);
        float p1 = __expf(sc1 - m);
        float sum = p0 + p1;
#pragma unroll
        for (int o = 16; o; o >>= 1) sum += __shfl_xor_sync(0xffffffffu, sum, o);
        float inv = 1.0f / sum;
        p0 *= inv; p1 *= inv;

        // AV: lane owns dims (2*lane, 2*lane+1); one LDS.64 per window step
        float o0 = 0.f, o1 = 0.f;
#pragma unroll
        for (int w = 0; w < WW; w++) {
            float pw = __shfl_sync(0xffffffffu, (w < 32) ? p0 : p1, w & 31);
            float2 vf = *(const float2*)(vs + (qi + w) * STR + 2 * lane);
            o0 = fmaf(pw, vf.x, o0);
            o1 = fmaf(pw, vf.y, o1);
        }
        *(__half2*)(zh + (baseTok + sq) * D_MODEL + hoff + 2 * lane) =
            __floats2half2_rn(o0, o1);
    }
}

// ---------------- Fused bias + residual + LayerNorm ----------------
__global__ __launch_bounds__(256) void ln_fused_kernel(
    const float* __restrict__ c, const float* __restrict__ bias,
    const float* __restrict__ res, const float* __restrict__ g,
    const float* __restrict__ be, float* __restrict__ y, __half* __restrict__ yh)
{
    const int row = blockIdx.x;
    const int tid = threadIdx.x;
    float4 v = ((const float4*)(c + (size_t)row * D_MODEL))[tid];
    float4 bb4 = ((const float4*)bias)[tid];
    float4 rr4 = ((const float4*)(res + (size_t)row * D_MODEL))[tid];
    v.x += bb4.x + rr4.x; v.y += bb4.y + rr4.y;
    v.z += bb4.z + rr4.z; v.w += bb4.w + rr4.w;

    float s  = v.x + v.y + v.z + v.w;
    float ss = v.x * v.x + v.y * v.y + v.z * v.z + v.w * v.w;

    __shared__ float red[2][8];
#pragma unroll
    for (int o = 16; o; o >>= 1) {
        s  += __shfl_xor_sync(0xffffffffu, s, o);
        ss += __shfl_xor_sync(0xffffffffu, ss, o);
    }
    int w = tid >> 5, l = tid & 31;
    if (l == 0) { red[0][w] = s; red[1][w] = ss; }
    __syncthreads();
    if (tid == 0) {
        float ts = 0.f, tss = 0.f;
#pragma unroll
        for (int i = 0; i < 8; i++) { ts += red[0][i]; tss += red[1][i]; }
        red[0][0] = ts; red[1][0] = tss;
    }
    __syncthreads();
    s = red[0][0]; ss = red[1][0];
    const float mean = s * (1.0f / D_MODEL);
    const float var  = ss * (1.0f / D_MODEL) - mean * mean;
    const float rstd = rsqrtf(var + 1e-5f);

    float4 gg = ((const float4*)g)[tid];
    float4 be4 = ((const float4*)be)[tid];
    float4 o;
    o.x = (v.x - mean) * rstd * gg.x + be4.x;
    o.y = (v.y - mean) * rstd * gg.y + be4.y;
    o.z = (v.z - mean) * rstd * gg.z + be4.z;
    o.w = (v.w - mean) * rstd * gg.w + be4.w;
    ((float4*)(y + (size_t)row * D_MODEL))[tid] = o;
    if (yh) {
        ((__half2*)(yh + (size_t)row * D_MODEL))[tid * 2 + 0] = __floats2half2_rn(o.x, o.y);
        ((__half2*)(yh + (size_t)row * D_MODEL))[tid * 2 + 1] = __floats2half2_rn(o.z, o.w);
    }
}

// ---------------- Orchestration ----------------
static inline void hgemm_go(const __half* A, const __half* B, float* Cf, __half* Ch,
                            int M, int N, int K, int ldc, int mode, const float* bias)
{
    dim3 grid(N / 128, M / 128);
    hgemm<<<grid, 256, HGEMM_SMEM>>>(A, B, Cf, Ch, M, N, K, ldc, mode, bias);
}

extern "C" void kernel_launch(void* const* d_in, const int* in_sizes, int n_in,
                              void* d_out, int out_size)
{
    (void)in_sizes; (void)n_in; (void)out_size;
    const float* src   = (const float*)d_in[0];
    const float* wq    = (const float*)d_in[1];
    const float* bq    = (const float*)d_in[2];
    const float* wk    = (const float*)d_in[3];
    const float* bk    = (const float*)d_in[4];
    const float* wv    = (const float*)d_in[5];
    const float* bv    = (const float*)d_in[6];
    const float* wo    = (const float*)d_in[7];
    const float* bo    = (const float*)d_in[8];
    const float* rel   = (const float*)d_in[9];
    const float* w1    = (const float*)d_in[10];
    const float* b1    = (const float*)d_in[11];
    const float* w2    = (const float*)d_in[12];
    const float* b2    = (const float*)d_in[13];
    const float* g1    = (const float*)d_in[14];
    const float* beta1 = (const float*)d_in[15];
    const float* g2    = (const float*)d_in[16];
    const float* beta2 = (const float*)d_in[17];
    float* out = (float*)d_out;

    float *qkv, *c1, *x1;
    __half *srch, *zhp, *x1h, *c2h, *wqkvh, *woh, *w1h, *w2h;
    cudaGetSymbolAddress((void**)&qkv,   g_qkv);
    cudaGetSymbolAddress((void**)&c1,    g_c1);
    cudaGetSymbolAddress((void**)&x1,    g_x1);
    cudaGetSymbolAddress((void**)&srch,  g_srch);
    cudaGetSymbolAddress((void**)&zhp,   g_zh);
    cudaGetSymbolAddress((void**)&x1h,   g_x1h);
    cudaGetSymbolAddress((void**)&c2h,   g_c2h);
    cudaGetSymbolAddress((void**)&wqkvh, g_wqkvh);
    cudaGetSymbolAddress((void**)&woh,   g_woh);
    cudaGetSymbolAddress((void**)&w1h,   g_w1h);
    cudaGetSymbolAddress((void**)&w2h,   g_w2h);

    cudaFuncSetAttribute(hgemm, cudaFuncAttributeMaxDynamicSharedMemorySize, HGEMM_SMEM);
    cudaFuncSetAttribute(attn_kernel, cudaFuncAttributeMaxDynamicSharedMemorySize, ATTN_SMEM);

    // 0) one merged conversion launch
    convert_all_kernel<<<SEG6 / 256, 256>>>(src, wq, wk, wv, wo, w1, w2,
                                            srch, wqkvh, woh, w1h, w2h);

    // 1) fused QKV projection -> fp32 qkv (ldc 3072); biases folded into attention
    hgemm_go(srch, wqkvh, qkv, nullptr, NTOK, 3 * D_MODEL, D_MODEL, 3 * D_MODEL, 0, nullptr);

    // 2) attention -> z (half)
    attn_kernel<<<dim3(SS / TS, NHEAD, BB), 256, ATTN_SMEM>>>(qkv, bq, bk, bv, rel, zhp);

    // 3) out-proj -> c1 fp32; fused bias+residual+LN1 -> x1 (fp32 + half)
    hgemm_go(zhp, woh, c1, nullptr, NTOK, D_MODEL, D_MODEL, D_MODEL, 0, nullptr);
    ln_fused_kernel<<<NTOK, 256>>>(c1, bo, src, g1, beta1, x1, x1h);

    // 4) FFN1: bias+relu fused, half output
    hgemm_go(x1h, w1h, nullptr, c2h, NTOK, DFF, D_MODEL, DFF, 1, b1);
    // 5) FFN2 -> c1 fp32; fused bias+residual+LN2 -> out
    hgemm_go(c2h, w2h, c1, nullptr, NTOK, D_MODEL, DFF, D_MODEL, 0, nullptr);
    ln_fused_kernel<<<NTOK, 256>>>(c1, b2, x1, g2, beta2, out, nullptr);
}

// round 12
// speedup vs baseline: 1.4262x; 1.4262x over previous
#include <cuda_runtime.h>
#include <cuda_fp16.h>
#include <cstdint>

// ---------------- Problem constants ----------------
#define D_MODEL 1024
#define NHEAD   16
#define DHEAD   64
#define DFF     4096
#define BB      2
#define SS      2048
#define RR      25
#define WW      51
#define KCLIP   5
#define NTOK    (BB * SS)

// ---------------- Scratch ----------------
__device__ float  g_qkv[(size_t)NTOK * 3 * D_MODEL];   // fp32 Q|K|V (ldc=3072)
__device__ float  g_c1 [(size_t)NTOK * D_MODEL];
__device__ float  g_x1 [(size_t)NTOK * D_MODEL];
__device__ __half g_srch[(size_t)NTOK * D_MODEL];
__device__ __half g_zh  [(size_t)NTOK * D_MODEL];
__device__ __half g_x1h [(size_t)NTOK * D_MODEL];
__device__ __half g_c2h [(size_t)NTOK * DFF];
__device__ __half g_wqkvh[(size_t)3 * D_MODEL * D_MODEL]; // wq|wk|wv rows
__device__ __half g_woh[(size_t)D_MODEL * D_MODEL];
__device__ __half g_w1h[(size_t)DFF * D_MODEL];
__device__ __half g_w2h[(size_t)D_MODEL * DFF];

// ---------------- helpers ----------------
__device__ __forceinline__ uint32_t smem_u32(const void* p) {
    uint32_t a;
    asm("{ .reg .u64 t; cvta.to.shared.u64 t, %1; cvt.u32.u64 %0, t; }" : "=r"(a) : "l"(p));
    return a;
}
__device__ __forceinline__ void cpasync16(uint32_t s, const void* g) {
    asm volatile("cp.async.cg.shared.global [%0], [%1], 16;\n" :: "r"(s), "l"(g));
}
__device__ __forceinline__ void ldm_x4(uint32_t& r0, uint32_t& r1, uint32_t& r2, uint32_t& r3,
                                       uint32_t addr) {
    asm volatile("ldmatrix.sync.aligned.m8n8.x4.shared.b16 {%0,%1,%2,%3}, [%4];"
                 : "=r"(r0), "=r"(r1), "=r"(r2), "=r"(r3) : "r"(addr));
}
__device__ __forceinline__ void mma16816(float* d, const uint32_t* a, uint32_t b0, uint32_t b1) {
    asm volatile("mma.sync.aligned.m16n8k16.row.col.f32.f16.f16.f32 "
                 "{%0,%1,%2,%3}, {%4,%5,%6,%7}, {%8,%9}, {%0,%1,%2,%3};"
                 : "+f"(d[0]), "+f"(d[1]), "+f"(d[2]), "+f"(d[3])
                 : "r"(a[0]), "r"(a[1]), "r"(a[2]), "r"(a[3]), "r"(b0), "r"(b1));
}

// ---------------- fp16 GEMM (exact R10-proven structure) ----------------
// C[M,N] = A[M,K] @ B[N,K]^T ; mode 0: fp32 out; 1: half bias+relu; 2: half bias
#define ST_A 10240              // 128 rows * 80B
#define ST_STAGE 20480          // A + B
#define HGEMM_SMEM (3 * ST_STAGE)

__global__ __launch_bounds__(256, 2) void hgemm(
    const __half* __restrict__ A, const __half* __restrict__ B,
    float* __restrict__ Cf, __half* __restrict__ Ch,
    int M, int N, int K, int ldc, int mode, const float* __restrict__ bias)
{
    extern __shared__ char smem[];
    const uint32_t sb = smem_u32(smem);
    const int tid = threadIdx.x;
    const int bm = blockIdx.y * 128;
    const int bn = blockIdx.x * 128;
    const int niter = K >> 5;

    const int pr = tid >> 1;            // row 0..127
    const int pc = (tid & 1) * 2;       // chunk base 0 or 2
    const __half* Agp = A + (size_t)(bm + pr) * K + pc * 8;
    const __half* Bgp = B + (size_t)(bn + pr) * K + pc * 8;
    const uint32_t sOff = (uint32_t)(pr * 5 + pc) * 16;

#define LOADSTAGE(s, it) do {                                     \
        uint32_t as_ = sb + (s) * ST_STAGE + sOff;                \
        const __half* ag_ = Agp + (size_t)(it) * 32;              \
        const __half* bg_ = Bgp + (size_t)(it) * 32;              \
        cpasync16(as_,            ag_);                           \
        cpasync16(as_ + 16,       ag_ + 8);                       \
        cpasync16(as_ + ST_A,     bg_);                           \
        cpasync16(as_ + ST_A + 16, bg_ + 8);                      \
    } while (0)
#define COMMIT() asm volatile("cp.async.commit_group;\n")

    const int warp = tid >> 5;
    const int lane = tid & 31;
    const int wm = (warp & 1) * 64;
    const int wn = (warp >> 1) * 32;
    const int grp = lane >> 3;
    const int lr  = lane & 7;
    const int lrow = (grp & 1) * 8 + lr;
    const int lchk = grp >> 1;

    float acc[4][4][4];
#pragma unroll
    for (int i = 0; i < 4; i++)
#pragma unroll
        for (int j = 0; j < 4; j++)
#pragma unroll
            for (int t = 0; t < 4; t++) acc[i][j][t] = 0.f;

    LOADSTAGE(0, 0); COMMIT();
    LOADSTAGE(1, 1); COMMIT();

    int stage = 0;
    for (int it = 0; it < niter; it++) {
        if (it + 2 < niter) LOADSTAGE((it + 2) % 3, it + 2);
        COMMIT();
        asm volatile("cp.async.wait_group 2;\n");
        __syncthreads();

        const uint32_t aS = sb + stage * ST_STAGE;
        const uint32_t bS = aS + ST_A;
#pragma unroll
        for (int ks = 0; ks < 2; ks++) {
            uint32_t af[4][4], bf[2][4];
#pragma unroll
            for (int mt = 0; mt < 4; mt++) {
                uint32_t addr = aS + (uint32_t)(((wm + mt * 16 + lrow) * 5 + ks * 2 + lchk) * 16);
                ldm_x4(af[mt][0], af[mt][1], af[mt][2], af[mt][3], addr);
            }
#pragma unroll
            for (int nc = 0; nc < 2; nc++) {
                uint32_t addr = bS + (uint32_t)(((wn + nc * 16 + lrow) * 5 + ks * 2 + lchk) * 16);
                ldm_x4(bf[nc][0], bf[nc][1], bf[nc][2], bf[nc][3], addr);
            }
#pragma unroll
            for (int mt = 0; mt < 4; mt++)
#pragma unroll
                for (int nj = 0; nj < 4; nj++) {
                    int nc = nj >> 1, sub = nj & 1;
                    mma16816(acc[mt][nj], af[mt], bf[nc][sub], bf[nc][sub + 2]);
                }
        }
        __syncthreads();
        stage = (stage + 1) == 3 ? 0 : stage + 1;
    }
#undef LOADSTAGE
#undef COMMIT

    const int qrow = lane >> 2;
    const int qcol = (lane & 3) * 2;
#pragma unroll
    for (int mt = 0; mt < 4; mt++) {
        const int row0 = bm + wm + mt * 16 + qrow;
#pragma unroll
        for (int nj = 0; nj < 4; nj++) {
            const int col = bn + wn + nj * 8 + qcol;
            if (mode == 0) {
                *(float2*)(Cf + (size_t)row0 * ldc + col) =
                    make_float2(acc[mt][nj][0], acc[mt][nj][1]);
                *(float2*)(Cf + (size_t)(row0 + 8) * ldc + col) =
                    make_float2(acc[mt][nj][2], acc[mt][nj][3]);
            } else {
                float b0 = bias[col], b1 = bias[col + 1];
                float v0 = acc[mt][nj][0] + b0, v1 = acc[mt][nj][1] + b1;
                float v2 = acc[mt][nj][2] + b0, v3 = acc[mt][nj][3] + b1;
                if (mode == 1) {
                    v0 = fmaxf(v0, 0.f); v1 = fmaxf(v1, 0.f);
                    v2 = fmaxf(v2, 0.f); v3 = fmaxf(v3, 0.f);
                }
                *(__half2*)(Ch + (size_t)row0 * ldc + col) = __floats2half2_rn(v0, v1);
                *(__half2*)(Ch + (size_t)(row0 + 8) * ldc + col) = __floats2half2_rn(v2, v3);
            }
        }
    }
}

// ---------------- merged fp32 -> fp16 convert (all operands, one launch) ----------------
#define SEG0 1048576   // src end (float4 units)
#define SEG1 1310720   // wq end
#define SEG2 1572864   // wk end
#define SEG3 1835008   // wv end
#define SEG4 2097152   // wo end
#define SEG5 3145728   // w1 end
#define SEG6 4194304   // w2 end
__global__ void convert_all_kernel(
    const float* __restrict__ src, const float* __restrict__ wq,
    const float* __restrict__ wk, const float* __restrict__ wv,
    const float* __restrict__ wo, const float* __restrict__ w1,
    const float* __restrict__ w2,
    __half* __restrict__ srch, __half* __restrict__ wqkvh,
    __half* __restrict__ woh, __half* __restrict__ w1h, __half* __restrict__ w2h)
{
    int i = blockIdx.x * blockDim.x + threadIdx.x;
    const float* s; __half* d; int off;
    if      (i < SEG0) { s = src; d = srch;  off = i; }
    else if (i < SEG1) { s = wq;  d = wqkvh; off = i - SEG0; }
    else if (i < SEG2) { s = wk;  d = wqkvh + (size_t)D_MODEL * D_MODEL; off = i - SEG1; }
    else if (i < SEG3) { s = wv;  d = wqkvh + 2 * (size_t)D_MODEL * D_MODEL; off = i - SEG2; }
    else if (i < SEG4) { s = wo;  d = woh;  off = i - SEG3; }
    else if (i < SEG5) { s = w1;  d = w1h;  off = i - SEG4; }
    else if (i < SEG6) { s = w2;  d = w2h;  off = i - SEG5; }
    else return;
    float4 v = ((const float4*)s)[off];
    ((__half2*)d)[off * 2 + 0] = __floats2half2_rn(v.x, v.y);
    ((__half2*)d)[off * 2 + 1] = __floats2half2_rn(v.z, v.w);
}

// ---------------- Windowed relative attention (fp32, vectorized smem) ----------------
#define TS 64
#define KROWS (TS + 2 * RR)   // 114
#define STR 68                // floats per row: 272B, 16B-aligned
#define ATTN_SMEM ((KROWS * 2 + TS + 11) * STR * 4)

__global__ __launch_bounds__(256) void attn_kernel(
    const float* __restrict__ qkv,
    const float* __restrict__ bq, const float* __restrict__ bk,
    const float* __restrict__ bv, const float* __restrict__ rel,
    __half* __restrict__ zh)
{
    extern __shared__ float sm[];
    float* ks = sm;                   // KROWS x STR
    float* vs = ks + KROWS * STR;     // KROWS x STR
    float* qs = vs + KROWS * STR;     // TS x STR
    float* rs = qs + TS * STR;        // 11 x STR

    const int h  = blockIdx.y;
    const int b  = blockIdx.z;
    const int s0 = blockIdx.x * TS;
    const int tid = threadIdx.x;
    const size_t baseTok = (size_t)b * SS;
    const int hoff = h * DHEAD;

    // K, V window rows (16 float4 chunks per row)
    for (int idx = tid; idx < KROWS * 16; idx += 256) {
        int i = idx >> 4;
        int d = (idx & 15);
        int t = min(max(s0 - RR + i, 0), SS - 1);
        const float* row = qkv + (baseTok + t) * (3 * D_MODEL);
        float4 k4 = *(const float4*)(row + D_MODEL + hoff + d * 4);
        float4 b4 = *(const float4*)(bk + hoff + d * 4);
        *(float4*)(ks + i * STR + d * 4) =
            make_float4(k4.x + b4.x, k4.y + b4.y, k4.z + b4.z, k4.w + b4.w);
        float4 v4 = *(const float4*)(row + 2 * D_MODEL + hoff + d * 4);
        float4 c4 = *(const float4*)(bv + hoff + d * 4);
        *(float4*)(vs + i * STR + d * 4) =
            make_float4(v4.x + c4.x, v4.y + c4.y, v4.z + c4.z, v4.w + c4.w);
    }
    // Q rows
    for (int idx = tid; idx < TS * 16; idx += 256) {
        int i = idx >> 4;
        int d = (idx & 15);
        float4 q4 = *(const float4*)(qkv + (baseTok + s0 + i) * (3 * D_MODEL) + hoff + d * 4);
        float4 b4 = *(const float4*)(bq + hoff + d * 4);
        *(float4*)(qs + i * STR + d * 4) =
            make_float4(q4.x + b4.x, q4.y + b4.y, q4.z + b4.z, q4.w + b4.w);
    }
    // rel rows
    for (int idx = tid; idx < 11 * 16; idx += 256) {
        int r = idx >> 4;
        int d = (idx & 15);
        *(float4*)(rs + r * STR + d * 4) = *(const float4*)(rel + r * DHEAD + d * 4);
    }
    __syncthreads();

    const int warp = tid >> 5;
    const int lane = tid & 31;
    const float scale = 0.125f;

    for (int qi = warp; qi < TS; qi += 8) {
        const int sq = s0 + qi;
        const float4* q4 = (const float4*)(qs + qi * STR);

        // hoisted q . rel[rid] (lanes 0..10)
        float qr = 0.f;
        if (lane < 11) {
            const float4* rp = (const float4*)(rs + lane * STR);
#pragma unroll
            for (int i = 0; i < 16; i++) {
                float4 qv = q4[i], rv = rp[i];
                qr = fmaf(qv.x, rv.x, qr); qr = fmaf(qv.y, rv.y, qr);
                qr = fmaf(qv.z, rv.z, qr); qr = fmaf(qv.w, rv.w, qr);
            }
        }

        const int w0 = lane;
        const int w1 = lane + 32;
        const bool has1 = (w1 < WW);
        int rid0 = min(max(w0 - RR, -KCLIP), KCLIP) + KCLIP;
        int rid1 = min(max(w1 - RR, -KCLIP), KCLIP) + KCLIP;
        float qr0 = __shfl_sync(0xffffffffu, qr, rid0);
        float qr1 = __shfl_sync(0xffffffffu, qr, rid1);
        const float4* k0p = (const float4*)(ks + (qi + w0) * STR);
        const float4* k1p = (const float4*)(ks + (qi + (has1 ? w1 : 0)) * STR);

        float a0 = 0.f, a1 = 0.f;
#pragma unroll
        for (int i = 0; i < 16; i++) {
            float4 qv = q4[i], f0 = k0p[i], f1 = k1p[i];
            a0 = fmaf(qv.x, f0.x, a0); a0 = fmaf(qv.y, f0.y, a0);
            a0 = fmaf(qv.z, f0.z, a0); a0 = fmaf(qv.w, f0.w, a0);
            a1 = fmaf(qv.x, f1.x, a1); a1 = fmaf(qv.y, f1.y, a1);
            a1 = fmaf(qv.z, f1.z, a1); a1 = fmaf(qv.w, f1.w, a1);
        }
        a0 += qr0;
        a1 += qr1;
        int j0 = sq + w0 - RR;
        int j1 = sq + w1 - RR;
        float sc0 = (j0 >= 0 && j0 < SS) ? a0 * scale : -1e30f;
        float sc1 = (has1 && j1 >= 0 && j1 < SS) ? a1 * scale : -1e30f;

        float m = fmaxf(sc0, sc1);
#pragma unroll
        for (int o = 16; o; o >>= 1) m = fmaxf(m, __shfl_xor_sync(0xffffffffu, m, o));
        float p0 = __expf(sc0 - m);
        float p1 = __expf(sc1 - m);
        float sum = p0 + p1;
#pragma unroll
        for (int o = 16; o; o >>= 1) sum += __shfl_xor_sync(0xffffffffu, sum, o);
        float inv = 1.0f / sum;
        p0 *= inv; p1 *= inv;

        // AV: lane owns dims (2*lane, 2*lane+1); one LDS.64 per window step
        float o0 = 0.f, o1 = 0.f;
#pragma unroll
        for (int w = 0; w < WW; w++) {
            float pw = __shfl_sync(0xffffffffu, (w < 32) ? p0 : p1, w & 31);
            float2 vf = *(const float2*)(vs + (qi + w) * STR + 2 * lane);
            o0 = fmaf(pw, vf.x, o0);
            o1 = fmaf(pw, vf.y, o1);
        }
        *(__half2*)(zh + (baseTok + sq) * D_MODEL + hoff + 2 * lane) =
            __floats2half2_rn(o0, o1);
    }
}

// ---------------- Fused bias + residual + LayerNorm ----------------
__global__ __launch_bounds__(256) void ln_fused_kernel(
    const float* __restrict__ c, const float* __restrict__ bias,
    const float* __restrict__ res, const float* __restrict__ g,
    const float* __restrict__ be, float* __restrict__ y, __half* __restrict__ yh)
{
    const int row = blockIdx.x;
    const int tid = threadIdx.x;
    float4 v = ((const float4*)(c + (size_t)row * D_MODEL))[tid];
    float4 bb4 = ((const float4*)bias)[tid];
    float4 rr4 = ((const float4*)(res + (size_t)row * D_MODEL))[tid];
    v.x += bb4.x + rr4.x; v.y += bb4.y + rr4.y;
    v.z += bb4.z + rr4.z; v.w += bb4.w + rr4.w;

    float s  = v.x + v.y + v.z + v.w;
    float ss = v.x * v.x + v.y * v.y + v.z * v.z + v.w * v.w;

    __shared__ float red[2][8];
#pragma unroll
    for (int o = 16; o; o >>= 1) {
        s  += __shfl_xor_sync(0xffffffffu, s, o);
        ss += __shfl_xor_sync(0xffffffffu, ss, o);
    }
    int w = tid >> 5, l = tid & 31;
    if (l == 0) { red[0][w] = s; red[1][w] = ss; }
    __syncthreads();
    if (tid == 0) {
        float ts = 0.f, tss = 0.f;
#pragma unroll
        for (int i = 0; i < 8; i++) { ts += red[0][i]; tss += red[1][i]; }
        red[0][0] = ts; red[1][0] = tss;
    }
    __syncthreads();
    s = red[0][0]; ss = red[1][0];
    const float mean = s * (1.0f / D_MODEL);
    const float var  = ss * (1.0f / D_MODEL) - mean * mean;
    const float rstd = rsqrtf(var + 1e-5f);

    float4 gg = ((const float4*)g)[tid];
    float4 be4 = ((const float4*)be)[tid];
    float4 o;
    o.x = (v.x - mean) * rstd * gg.x + be4.x;
    o.y = (v.y - mean) * rstd * gg.y + be4.y;
    o.z = (v.z - mean) * rstd * gg.z + be4.z;
    o.w = (v.w - mean) * rstd * gg.w + be4.w;
    ((float4*)(y + (size_t)row * D_MODEL))[tid] = o;
    if (yh) {
        ((__half2*)(yh + (size_t)row * D_MODEL))[tid * 2 + 0] = __floats2half2_rn(o.x, o.y);
        ((__half2*)(yh + (size_t)row * D_MODEL))[tid * 2 + 1] = __floats2half2_rn(o.z, o.w);
    }
}

// ---------------- Orchestration ----------------
static inline void hgemm_go(const __half* A, const __half* B, float* Cf, __half* Ch,
                            int M, int N, int K, int ldc, int mode, const float* bias)
{
    dim3 grid(N / 128, M / 128);
    hgemm<<<grid, 256, HGEMM_SMEM>>>(A, B, Cf, Ch, M, N, K, ldc, mode, bias);
}

extern "C" void kernel_launch(void* const* d_in, const int* in_sizes, int n_in,
                              void* d_out, int out_size)
{
    (void)in_sizes; (void)n_in; (void)out_size;
    const float* src   = (const float*)d_in[0];
    const float* wq    = (const float*)d_in[1];
    const float* bq    = (const float*)d_in[2];
    const float* wk    = (const float*)d_in[3];
    const float* bk    = (const float*)d_in[4];
    const float* wv    = (const float*)d_in[5];
    const float* bv    = (const float*)d_in[6];
    const float* wo    = (const float*)d_in[7];
    const float* bo    = (const float*)d_in[8];
    const float* rel   = (const float*)d_in[9];
    const float* w1    = (const float*)d_in[10];
    const float* b1    = (const float*)d_in[11];
    const float* w2    = (const float*)d_in[12];
    const float* b2    = (const float*)d_in[13];
    const float* g1    = (const float*)d_in[14];
    const float* beta1 = (const float*)d_in[15];
    const float* g2    = (const float*)d_in[16];
    const float* beta2 = (const float*)d_in[17];
    float* out = (float*)d_out;

    float *qkv, *c1, *x1;
    __half *srch, *zhp, *x1h, *c2h, *wqkvh, *woh, *w1h, *w2h;
    cudaGetSymbolAddress((void**)&qkv,   g_qkv);
    cudaGetSymbolAddress((void**)&c1,    g_c1);
    cudaGetSymbolAddress((void**)&x1,    g_x1);
    cudaGetSymbolAddress((void**)&srch,  g_srch);
    cudaGetSymbolAddress((void**)&zhp,   g_zh);
    cudaGetSymbolAddress((void**)&x1h,   g_x1h);
    cudaGetSymbolAddress((void**)&c2h,   g_c2h);
    cudaGetSymbolAddress((void**)&wqkvh, g_wqkvh);
    cudaGetSymbolAddress((void**)&woh,   g_woh);
    cudaGetSymbolAddress((void**)&w1h,   g_w1h);
    cudaGetSymbolAddress((void**)&w2h,   g_w2h);

    cudaFuncSetAttribute(hgemm, cudaFuncAttributeMaxDynamicSharedMemorySize, HGEMM_SMEM);
    cudaFuncSetAttribute(attn_kernel, cudaFuncAttributeMaxDynamicSharedMemorySize, ATTN_SMEM);

    // 0) one merged conversion launch
    convert_all_kernel<<<SEG6 / 256, 256>>>(src, wq, wk, wv, wo, w1, w2,
                                            srch, wqkvh, woh, w1h, w2h);

    // 1) fused QKV projection -> fp32 qkv (ldc 3072); biases folded into attention
    hgemm_go(srch, wqkvh, qkv, nullptr, NTOK, 3 * D_MODEL, D_MODEL, 3 * D_MODEL, 0, nullptr);

    // 2) attention -> z (half)
    attn_kernel<<<dim3(SS / TS, NHEAD, BB), 256, ATTN_SMEM>>>(qkv, bq, bk, bv, rel, zhp);

    // 3) out-proj -> c1 fp32; fused bias+residual+LN1 -> x1 (fp32 + half)
    hgemm_go(zhp, woh, c1, nullptr, NTOK, D_MODEL, D_MODEL, D_MODEL, 0, nullptr);
    ln_fused_kernel<<<NTOK, 256>>>(c1, bo, src, g1, beta1, x1, x1h);

    // 4) FFN1: bias+relu fused, half output
    hgemm_go(x1h, w1h, nullptr, c2h, NTOK, DFF, D_MODEL, DFF, 1, b1);
    // 5) FFN2 -> c1 fp32; fused bias+residual+LN2 -> out
    hgemm_go(c2h, w2h, c1, nullptr, NTOK, D_MODEL, DFF, D_MODEL, 0, nullptr);
    ln_fused_kernel<<<NTOK, 256>>>(c1, b2, x1, g2, beta2, out, nullptr);
}